// round 15
// baseline (speedup 1.0000x reference)
#include <cuda_runtime.h>

// RoiPooling: torchvision roi_pool (max), OUT=7x7, SCALE=0.125
// input:  (4, 256, 100, 152) fp32 NCHW
// boxes:  (K, 5) fp32  [batch_idx, x1, y1, x2, y2] image coords
// output: (K, 256, 7, 7) fp32
//
// SEMANTIC (verified R4): XLA rewrites (x / 7.0f) -> x * (1/7.0f); bin sizes
// MUST be computed via __fmul_rn(x, 1.0f/7.0f) to bit-match the reference.
//
// Pipeline (2 launches):
//  1) fused: transpose NCHW->NHWC (blocks [0,3040)) + bounds prep (rest)
//  2) main gather: CTA=(roi, 128ch half), 7 warps; DIAGONAL bin assignment
//     (warp w, task t -> ph=(w+t)%7, pw=t) for intra-CTA balance; dual
//     accumulators break the FMAX chain; __launch_bounds__(224,8) caps
//     regs at 36 -> 8 resident CTAs/SM.

static constexpr int N_   = 4;
static constexpr int C_   = 256;
static constexpr int H_   = 100;
static constexpr int W_   = 152;
static constexpr int HW_  = H_ * W_;
static constexpr int C4_  = C_ / 4;            // float4 per cell = 64
static constexpr int KMAX = 8192;

static constexpr int TBLK = (HW_ / 160) * (C_ / 32) * N_;   // 3040

__device__ float        g_xT[N_ * HW_ * C_];   // NHWC scratch (62.3 MB)
__device__ unsigned int g_bounds[KMAX * 49];   // hs|he<<8|ws<<16|we<<24
__device__ int          g_baseT[KMAX];         // b * HW_ * C_

// ---------- 1) fused transpose + bounds prep (R14-exact) ----------
__global__ __launch_bounds__(256)
void transpose_and_prep(const float* __restrict__ x,
                        const float* __restrict__ boxes,
                        int kb_total)
{
    const int bx = blockIdx.x;

    if (bx < TBLK) {
        __shared__ float tile[5][32][33];      // 21.1 KB
        const int b   = bx / 760;
        const int rem = bx - b * 760;
        const int c0  = (rem / 95) * 32;
        const int hw0 = (rem % 95) * 160;
        const int tx  = threadIdx.x & 31;
        const int ty4 = threadIdx.x >> 5;

        const float* src = x + ((size_t)b * C_) * HW_;
        float*       dst = g_xT + (size_t)b * HW_ * C_;

        #pragma unroll
        for (int j = 0; j < 5; ++j)
            #pragma unroll
            for (int i = 0; i < 4; ++i) {
                const int c = c0 + ty4 * 4 + i;
                tile[j][ty4 * 4 + i][tx] = src[(size_t)c * HW_ + hw0 + j * 32 + tx];
            }
        __syncthreads();
        #pragma unroll
        for (int j = 0; j < 5; ++j)
            #pragma unroll
            for (int i = 0; i < 4; ++i) {
                const int hw = hw0 + j * 32 + ty4 * 4 + i;
                dst[(size_t)hw * C_ + c0 + tx] = tile[j][tx][ty4 * 4 + i];
            }
    } else {
        const int i = (bx - TBLK) * 256 + threadIdx.x;
        if (i >= kb_total) return;
        const int bin = i % 49;
        const int k   = i / 49;
        const int pw  = bin % 7;
        const int ph  = bin / 7;

        const float* bxp = boxes + (size_t)k * 5;
        const int b  = (int)bxp[0];
        const int x1 = __float2int_rn(__fmul_rn(bxp[1], 0.125f));
        const int y1 = __float2int_rn(__fmul_rn(bxp[2], 0.125f));
        const int x2 = __float2int_rn(__fmul_rn(bxp[3], 0.125f));
        const int y2 = __float2int_rn(__fmul_rn(bxp[4], 0.125f));
        const int roi_w = max(x2 - x1 + 1, 1);
        const int roi_h = max(y2 - y1 + 1, 1);
        const float RCP7 = 1.0f / 7.0f;        // XLA reciprocal rewrite
        const float bin_h = __fmul_rn((float)roi_h, RCP7);
        const float bin_w = __fmul_rn((float)roi_w, RCP7);

        const int hs = min(max((int)floorf(__fmul_rn((float)ph,       bin_h)) + y1, 0), H_);
        const int he = min(max((int)ceilf (__fmul_rn((float)(ph + 1), bin_h)) + y1, 0), H_);
        const int ws = min(max((int)floorf(__fmul_rn((float)pw,       bin_w)) + x1, 0), W_);
        const int we = min(max((int)ceilf (__fmul_rn((float)(pw + 1), bin_w)) + x1, 0), W_);

        g_bounds[i] = (unsigned)hs | ((unsigned)he << 8)
                    | ((unsigned)ws << 16) | ((unsigned)we << 24);
        if (bin == 0) g_baseT[k] = b * HW_ * C_;
    }
}

// -------- 2) main gather: diagonal bins, dual accumulators ---------------
static constexpr int SPITCH = 33;              // float4 per bin row (pad)

__device__ __forceinline__ float4 f4max(float4 a, const float4 b) {
    a.x = fmaxf(a.x, b.x); a.y = fmaxf(a.y, b.y);
    a.z = fmaxf(a.z, b.z); a.w = fmaxf(a.w, b.w);
    return a;
}

__global__ __launch_bounds__(224, 8)
void roi_pool_nhwc4(float* __restrict__ out)
{
    __shared__ float4 sres[49 * SPITCH];       // 25.9 KB

    const int k    = blockIdx.x >> 1;
    const int half = blockIdx.x & 1;
    const int c0q  = half * 32;
    const int wid  = threadIdx.x >> 5;         // 0..6
    const int lane = threadIdx.x & 31;

    const float4* srcq = (const float4*)g_xT;
    const int baseq = (g_baseT[k] >> 2) + c0q + lane;
    const unsigned int* bnd = g_bounds + k * 49;

    const float NI = __int_as_float(0xff800000);

    #pragma unroll
    for (int t = 0; t < 7; ++t) {
        // diagonal assignment: each warp sees every row-height and
        // every column-width exactly once -> balanced warp work
        int ph = wid + t; if (ph >= 7) ph -= 7;
        const int bin = ph * 7 + t;            // pw = t

        const unsigned w32 = bnd[bin];
        const int hs =  w32        & 0xff;
        const int he = (w32 >> 8)  & 0xff;
        const int ws = (w32 >> 16) & 0xff;
        const int we = (w32 >> 24) & 0xff;

        // dual accumulators: row-r chain (m0) and row-r+1 chain (m1)
        float4 m0 = make_float4(NI, NI, NI, NI);
        float4 m1 = m0;
        int r = hs;
        for (; r + 1 < he; r += 2) {
            const int r0 = baseq + r * (W_ * C4_);
            const int r1 = r0 + (W_ * C4_);
            int cc = ws;
            for (; cc + 1 < we; cc += 2) {     // 4 independent LDG.128
                m0 = f4max(m0, srcq[r0 + cc * C4_]);
                m0 = f4max(m0, srcq[r0 + (cc + 1) * C4_]);
                m1 = f4max(m1, srcq[r1 + cc * C4_]);
                m1 = f4max(m1, srcq[r1 + (cc + 1) * C4_]);
            }
            if (cc < we) {
                m0 = f4max(m0, srcq[r0 + cc * C4_]);
                m1 = f4max(m1, srcq[r1 + cc * C4_]);
            }
        }
        if (r < he) {                          // tail row -> m0
            const int r0 = baseq + r * (W_ * C4_);
            int cc = ws;
            for (; cc + 1 < we; cc += 2) {
                m0 = f4max(m0, srcq[r0 + cc * C4_]);
                m1 = f4max(m1, srcq[r0 + (cc + 1) * C4_]);
            }
            if (cc < we)
                m0 = f4max(m0, srcq[r0 + cc * C4_]);
        }
        float4 m = f4max(m0, m1);
        if ((he <= hs) || (we <= ws))
            m = make_float4(0.f, 0.f, 0.f, 0.f);
        sres[bin * SPITCH + lane] = m;
    }
    __syncthreads();

    // coalesced write: out[k*12544 + (c0 + cloc)*49 + bin]
    const float* s = (const float*)sres;       // bin row = 132 floats
    float* dst = out + (size_t)k * (C_ * 49) + (size_t)(half * 128) * 49;
    for (int i = threadIdx.x; i < 128 * 49; i += 224) {   // 28 exact iters
        const int cloc = i / 49;
        const int bin  = i - cloc * 49;
        dst[i] = s[bin * (SPITCH * 4) + cloc];
    }
}

extern "C" void kernel_launch(void* const* d_in, const int* in_sizes, int n_in,
                              void* d_out, int out_size) {
    const float* x     = (const float*)d_in[0];
    const float* boxes = (const float*)d_in[1];
    float*       out   = (float*)d_out;
    const int K = in_sizes[1] / 5;               // boxes is (K, 5)

    const int kb_total    = K * 49;
    const int prep_blocks = (kb_total + 255) / 256;
    transpose_and_prep<<<TBLK + prep_blocks, 256>>>(x, boxes, kb_total);

    roi_pool_nhwc4<<<K * 2, 224>>>(out);
}

// round 16
// speedup vs baseline: 1.7279x; 1.7279x over previous
#include <cuda_runtime.h>

// RoiPooling: torchvision roi_pool (max), OUT=7x7, SCALE=0.125
// input:  (4, 256, 100, 152) fp32 NCHW
// boxes:  (K, 5) fp32  [batch_idx, x1, y1, x2, y2] image coords
// output: (K, 256, 7, 7) fp32
//
// SEMANTIC (verified R4): XLA rewrites (x / 7.0f) -> x * (1/7.0f); bin sizes
// MUST be computed via __fmul_rn(x, 1.0f/7.0f) to bit-match the reference.
//
// Pipeline (2 launches):
//  1) fused: transpose NCHW->NHWC (blocks [0,3040), __ldcs streaming reads)
//     + per-(roi,bin) bounds prep (remaining blocks)
//  2) main gather (R14-exact structure; regs=40/7 CTAs is the measured
//     optimum -- DO NOT cap registers, R15 spill regression): CTA=(roi,
//     128ch half), 7 warps, warp = ph row of 7 bins, lane = 4 channels,
//     2x2 float4 unroll. Output written with __stcs so the 103MB of
//     write-once data does not evict the L2-resident feature map.

static constexpr int N_   = 4;
static constexpr int C_   = 256;
static constexpr int H_   = 100;
static constexpr int W_   = 152;
static constexpr int HW_  = H_ * W_;
static constexpr int C4_  = C_ / 4;            // float4 per cell = 64
static constexpr int KMAX = 8192;

static constexpr int TBLK = (HW_ / 160) * (C_ / 32) * N_;   // 3040

__device__ float        g_xT[N_ * HW_ * C_];   // NHWC scratch (62.3 MB)
__device__ unsigned int g_bounds[KMAX * 49];   // hs|he<<8|ws<<16|we<<24
__device__ int          g_baseT[KMAX];         // b * HW_ * C_

// ---------- 1) fused transpose + bounds prep ----------
__global__ __launch_bounds__(256)
void transpose_and_prep(const float* __restrict__ x,
                        const float* __restrict__ boxes,
                        int kb_total)
{
    const int bx = blockIdx.x;

    if (bx < TBLK) {
        __shared__ float tile[5][32][33];      // 21.1 KB
        const int b   = bx / 760;
        const int rem = bx - b * 760;
        const int c0  = (rem / 95) * 32;
        const int hw0 = (rem % 95) * 160;
        const int tx  = threadIdx.x & 31;
        const int ty4 = threadIdx.x >> 5;

        const float* src = x + ((size_t)b * C_) * HW_;
        float*       dst = g_xT + (size_t)b * HW_ * C_;

        #pragma unroll
        for (int j = 0; j < 5; ++j)
            #pragma unroll
            for (int i = 0; i < 4; ++i) {
                const int c = c0 + ty4 * 4 + i;
                // read-once: streaming hint, don't pollute L2
                tile[j][ty4 * 4 + i][tx] =
                    __ldcs(&src[(size_t)c * HW_ + hw0 + j * 32 + tx]);
            }
        __syncthreads();
        #pragma unroll
        for (int j = 0; j < 5; ++j)
            #pragma unroll
            for (int i = 0; i < 4; ++i) {
                const int hw = hw0 + j * 32 + ty4 * 4 + i;
                dst[(size_t)hw * C_ + c0 + tx] = tile[j][tx][ty4 * 4 + i];
            }
    } else {
        const int i = (bx - TBLK) * 256 + threadIdx.x;
        if (i >= kb_total) return;
        const int bin = i % 49;
        const int k   = i / 49;
        const int pw  = bin % 7;
        const int ph  = bin / 7;

        const float* bxp = boxes + (size_t)k * 5;
        const int b  = (int)bxp[0];
        const int x1 = __float2int_rn(__fmul_rn(bxp[1], 0.125f));
        const int y1 = __float2int_rn(__fmul_rn(bxp[2], 0.125f));
        const int x2 = __float2int_rn(__fmul_rn(bxp[3], 0.125f));
        const int y2 = __float2int_rn(__fmul_rn(bxp[4], 0.125f));
        const int roi_w = max(x2 - x1 + 1, 1);
        const int roi_h = max(y2 - y1 + 1, 1);
        const float RCP7 = 1.0f / 7.0f;        // XLA reciprocal rewrite
        const float bin_h = __fmul_rn((float)roi_h, RCP7);
        const float bin_w = __fmul_rn((float)roi_w, RCP7);

        const int hs = min(max((int)floorf(__fmul_rn((float)ph,       bin_h)) + y1, 0), H_);
        const int he = min(max((int)ceilf (__fmul_rn((float)(ph + 1), bin_h)) + y1, 0), H_);
        const int ws = min(max((int)floorf(__fmul_rn((float)pw,       bin_w)) + x1, 0), W_);
        const int we = min(max((int)ceilf (__fmul_rn((float)(pw + 1), bin_w)) + x1, 0), W_);

        g_bounds[i] = (unsigned)hs | ((unsigned)he << 8)
                    | ((unsigned)ws << 16) | ((unsigned)we << 24);
        if (bin == 0) g_baseT[k] = b * HW_ * C_;
    }
}

// -------- 2) main gather (R14-exact + __stcs output) ----------------------
static constexpr int SPITCH = 33;              // float4 per bin row (pad)

__device__ __forceinline__ float4 f4max(float4 a, const float4 b) {
    a.x = fmaxf(a.x, b.x); a.y = fmaxf(a.y, b.y);
    a.z = fmaxf(a.z, b.z); a.w = fmaxf(a.w, b.w);
    return a;
}

__global__ __launch_bounds__(224)
void roi_pool_nhwc4(float* __restrict__ out)
{
    __shared__ float4 sres[49 * SPITCH];       // 25.9 KB

    const int k    = blockIdx.x >> 1;
    const int half = blockIdx.x & 1;
    const int c0q  = half * 32;
    const int wid  = threadIdx.x >> 5;         // 0..6
    const int lane = threadIdx.x & 31;

    const float4* srcq = (const float4*)g_xT;
    const int baseq = (g_baseT[k] >> 2) + c0q + lane;
    const unsigned int* bnd = g_bounds + k * 49;

    const float NI = __int_as_float(0xff800000);

    #pragma unroll
    for (int t = 0; t < 7; ++t) {              // exactly 7 bins per warp
        const int bin = wid * 7 + t;
        const unsigned w32 = bnd[bin];
        const int hs =  w32        & 0xff;
        const int he = (w32 >> 8)  & 0xff;
        const int ws = (w32 >> 16) & 0xff;
        const int we = (w32 >> 24) & 0xff;

        float4 m = make_float4(NI, NI, NI, NI);
        int r = hs;
        for (; r + 1 < he; r += 2) {
            const int r0 = baseq + r * (W_ * C4_);
            const int r1 = r0 + (W_ * C4_);
            int cc = ws;
            for (; cc + 1 < we; cc += 2) {     // 4 independent LDG.128
                m = f4max(m, srcq[r0 + cc * C4_]);
                m = f4max(m, srcq[r0 + (cc + 1) * C4_]);
                m = f4max(m, srcq[r1 + cc * C4_]);
                m = f4max(m, srcq[r1 + (cc + 1) * C4_]);
            }
            if (cc < we) {
                m = f4max(m, srcq[r0 + cc * C4_]);
                m = f4max(m, srcq[r1 + cc * C4_]);
            }
        }
        if (r < he) {
            const int r0 = baseq + r * (W_ * C4_);
            int cc = ws;
            for (; cc + 1 < we; cc += 2) {
                m = f4max(m, srcq[r0 + cc * C4_]);
                m = f4max(m, srcq[r0 + (cc + 1) * C4_]);
            }
            if (cc < we)
                m = f4max(m, srcq[r0 + cc * C4_]);
        }
        if ((he <= hs) || (we <= ws))
            m = make_float4(0.f, 0.f, 0.f, 0.f);
        sres[bin * SPITCH + lane] = m;
    }
    __syncthreads();

    // coalesced streaming write: out[k*12544 + (c0 + cloc)*49 + bin]
    // __stcs: write-once data must not evict the L2-resident feature map
    const float* s = (const float*)sres;       // bin row = 132 floats
    float* dst = out + (size_t)k * (C_ * 49) + (size_t)(half * 128) * 49;
    for (int i = threadIdx.x; i < 128 * 49; i += 224) {   // 28 exact iters
        const int cloc = i / 49;
        const int bin  = i - cloc * 49;
        __stcs(&dst[i], s[bin * (SPITCH * 4) + cloc]);
    }
}

extern "C" void kernel_launch(void* const* d_in, const int* in_sizes, int n_in,
                              void* d_out, int out_size) {
    const float* x     = (const float*)d_in[0];
    const float* boxes = (const float*)d_in[1];
    float*       out   = (float*)d_out;
    const int K = in_sizes[1] / 5;               // boxes is (K, 5)

    const int kb_total    = K * 49;
    const int prep_blocks = (kb_total + 255) / 256;
    transpose_and_prep<<<TBLK + prep_blocks, 256>>>(x, boxes, kb_total);

    roi_pool_nhwc4<<<K * 2, 224>>>(out);
}